// round 13
// baseline (speedup 1.0000x reference)
#include <cuda_runtime.h>
#include <cuda_bf16.h>
#include <math.h>
#include <stdint.h>

#define T_SEQ 4096
#define D_MODEL 1024
#define N_HEAD 16
#define C_HEAD 64
#define QKV_W 3072

// Scratch (device globals: allocation-guard safe)
__device__ float g_qkv[(size_t)T_SEQ * QKV_W];     // [T][3D], q|k|v sections
__device__ float g_attn[(size_t)T_SEQ * D_MODEL];  // [T][D] attention output
// Precomputed hi/lo bf16 (RoPE'd; Q pre-scaled by 1/8)
__device__ __nv_bfloat16 g_qh[(size_t)T_SEQ * D_MODEL];
__device__ __nv_bfloat16 g_ql[(size_t)T_SEQ * D_MODEL];
__device__ __nv_bfloat16 g_kh[(size_t)T_SEQ * D_MODEL];
__device__ __nv_bfloat16 g_kl[(size_t)T_SEQ * D_MODEL];
__device__ __nv_bfloat16 g_vh[(size_t)T_SEQ * D_MODEL];
__device__ __nv_bfloat16 g_vl[(size_t)T_SEQ * D_MODEL];

// ---------------------------------------------------------------------------
// Common helpers
// ---------------------------------------------------------------------------
__device__ __forceinline__ uint32_t smem_u32(const void* p) {
    return (uint32_t)__cvta_generic_to_shared(p);
}

__device__ __forceinline__ uint32_t pack_bf16(float x, float y) {
    __nv_bfloat162 t = __floats2bfloat162_rn(x, y);
    return *(uint32_t*)&t;
}

__device__ __forceinline__ void mma_bf16_16x8x8(float* c,
                                                uint32_t a0, uint32_t a1,
                                                uint32_t b0) {
    asm volatile(
        "mma.sync.aligned.m16n8k8.row.col.f32.bf16.bf16.f32 "
        "{%0,%1,%2,%3}, {%4,%5}, {%6}, {%0,%1,%2,%3};"
        : "+f"(c[0]), "+f"(c[1]), "+f"(c[2]), "+f"(c[3])
        : "r"(a0), "r"(a1), "r"(b0));
}

__device__ __forceinline__ void mma_bf16_16x8x16(float* c, const uint32_t* a,
                                                 uint32_t b0, uint32_t b1) {
    asm volatile(
        "mma.sync.aligned.m16n8k16.row.col.f32.bf16.bf16.f32 "
        "{%0,%1,%2,%3}, {%4,%5,%6,%7}, {%8,%9}, {%0,%1,%2,%3};"
        : "+f"(c[0]), "+f"(c[1]), "+f"(c[2]), "+f"(c[3])
        : "r"(a[0]), "r"(a[1]), "r"(a[2]), "r"(a[3]), "r"(b0), "r"(b1));
}

__device__ __forceinline__ void ldm_x2(uint32_t& r0, uint32_t& r1, uint32_t addr) {
    asm volatile("ldmatrix.sync.aligned.m8n8.x2.shared.b16 {%0,%1}, [%2];"
                 : "=r"(r0), "=r"(r1) : "r"(addr));
}

__device__ __forceinline__ void ldm_x2_trans(uint32_t& r0, uint32_t& r1, uint32_t addr) {
    asm volatile("ldmatrix.sync.aligned.m8n8.x2.trans.shared.b16 {%0,%1}, [%2];"
                 : "=r"(r0), "=r"(r1) : "r"(addr));
}

__device__ __forceinline__ void cpa16(uint32_t dst, const __nv_bfloat16* src) {
    asm volatile("cp.async.cg.shared.global [%0], [%1], 16;"
                 :: "r"(dst), "l"(__cvta_generic_to_global(src)));
}
__device__ __forceinline__ void cpa_commit() {
    asm volatile("cp.async.commit_group;");
}
template <int N>
__device__ __forceinline__ void cpa_wait() {
    asm volatile("cp.async.wait_group %0;" :: "n"(N));
}

// ---------------------------------------------------------------------------
// Split-bf16 tensor-core NT GEMM. MMA issue is TERM-MAJOR (all hh, then hl,
// then lh) so same-accumulator MMAs are 16 apart (pipelined at throughput).
// ---------------------------------------------------------------------------
#define BMg 128
#define BNg 128
#define BKg 32

__global__ void __launch_bounds__(256, 2)
gemm_nt_bf16x3_kernel(const float* __restrict__ A,
                      const float* __restrict__ B,
                      float* __restrict__ C,
                      int M, int N, int K) {
    __shared__ __nv_bfloat16 Ah[BMg][BKg + 2];
    __shared__ __nv_bfloat16 Al[BMg][BKg + 2];
    __shared__ __nv_bfloat16 Bh[BNg][BKg + 2];
    __shared__ __nv_bfloat16 Bl[BNg][BKg + 2];

    int tid = threadIdx.x;
    int warp = tid >> 5;
    int lane = tid & 31;
    int wm = warp >> 2;
    int wn = warp & 3;
    int g = lane >> 2;
    int tg = lane & 3;
    int m0 = blockIdx.y * BMg;
    int n0 = blockIdx.x * BNg;
    int wm0 = wm * 64;
    int wn0 = wn * 32;

    float acc[4][4][4] = {};

    for (int k0 = 0; k0 < K; k0 += BKg) {
#pragma unroll
        for (int i = 0; i < 4; i++) {
            int f = tid + i * 256;
            int r = f >> 3;
            int c = (f & 7) * 4;
            float4 va = *(const float4*)(A + (size_t)(m0 + r) * K + k0 + c);
            float xs[4] = {va.x, va.y, va.z, va.w};
#pragma unroll
            for (int j = 0; j < 4; j++) {
                __nv_bfloat16 hh = __float2bfloat16(xs[j]);
                Ah[r][c + j] = hh;
                Al[r][c + j] = __float2bfloat16(xs[j] - __bfloat162float(hh));
            }
            float4 vb = *(const float4*)(B + (size_t)(n0 + r) * K + k0 + c);
            float ys[4] = {vb.x, vb.y, vb.z, vb.w};
#pragma unroll
            for (int j = 0; j < 4; j++) {
                __nv_bfloat16 hh = __float2bfloat16(ys[j]);
                Bh[r][c + j] = hh;
                Bl[r][c + j] = __float2bfloat16(ys[j] - __bfloat162float(hh));
            }
        }
        __syncthreads();

#pragma unroll
        for (int kc = 0; kc < BKg; kc += 8) {
            uint32_t ah[4][2], al[4][2], bh[4], bl[4];
#pragma unroll
            for (int mt = 0; mt < 4; mt++) {
                int r = wm0 + mt * 16 + g;
                ah[mt][0] = *(const uint32_t*)&Ah[r][kc + tg * 2];
                ah[mt][1] = *(const uint32_t*)&Ah[r + 8][kc + tg * 2];
                al[mt][0] = *(const uint32_t*)&Al[r][kc + tg * 2];
                al[mt][1] = *(const uint32_t*)&Al[r + 8][kc + tg * 2];
            }
#pragma unroll
            for (int nt = 0; nt < 4; nt++) {
                int r = wn0 + nt * 8 + g;
                bh[nt] = *(const uint32_t*)&Bh[r][kc + tg * 2];
                bl[nt] = *(const uint32_t*)&Bl[r][kc + tg * 2];
            }
            // term-major: same-acc dependency distance = 16 MMAs
#pragma unroll
            for (int mt = 0; mt < 4; mt++)
#pragma unroll
                for (int nt = 0; nt < 4; nt++)
                    mma_bf16_16x8x8(acc[mt][nt], ah[mt][0], ah[mt][1], bh[nt]);
#pragma unroll
            for (int mt = 0; mt < 4; mt++)
#pragma unroll
                for (int nt = 0; nt < 4; nt++)
                    mma_bf16_16x8x8(acc[mt][nt], ah[mt][0], ah[mt][1], bl[nt]);
#pragma unroll
            for (int mt = 0; mt < 4; mt++)
#pragma unroll
                for (int nt = 0; nt < 4; nt++)
                    mma_bf16_16x8x8(acc[mt][nt], al[mt][0], al[mt][1], bh[nt]);
        }
        __syncthreads();
    }

#pragma unroll
    for (int mt = 0; mt < 4; mt++) {
        int r = m0 + wm0 + mt * 16 + g;
#pragma unroll
        for (int nt = 0; nt < 4; nt++) {
            int cb = n0 + wn0 + nt * 8 + tg * 2;
            *(float2*)&C[(size_t)r * N + cb] =
                make_float2(acc[mt][nt][0], acc[mt][nt][1]);
            *(float2*)&C[(size_t)(r + 8) * N + cb] =
                make_float2(acc[mt][nt][2], acc[mt][nt][3]);
        }
    }
}

// ---------------------------------------------------------------------------
// Fused RoPE + hi/lo bf16 conversion (unchanged).
// ---------------------------------------------------------------------------
__global__ void rope_convert_kernel(const float* __restrict__ qkv) {
    int idx = blockIdx.x * blockDim.x + threadIdx.x;   // 0 .. T*512-1
    int p = idx & 31;                // pair index within head
    int h = (idx >> 5) & 15;
    int t = idx >> 9;
    if (t >= T_SEQ) return;

    const float LOG_10000 = 9.210340371976184f;
    float inv_freq = expf(-(2.f * (float)p / (float)C_HEAD) * LOG_10000);
    float ang = (float)t * inv_freq;
    float s, c;
    sincosf(ang, &s, &c);

    int d = h * C_HEAD + 2 * p;
    size_t qbase = (size_t)t * QKV_W + d;
    size_t obase = (size_t)t * D_MODEL + d;

    {
        float x1 = qkv[qbase], x2 = qkv[qbase + 1];
        float r1 = (x1 * c - x2 * s) * 0.125f;
        float r2 = (x2 * c + x1 * s) * 0.125f;
        __nv_bfloat16 h1 = __float2bfloat16(r1), h2 = __float2bfloat16(r2);
        *(__nv_bfloat162*)&g_qh[obase] = __nv_bfloat162(h1, h2);
        *(__nv_bfloat162*)&g_ql[obase] = __nv_bfloat162(
            __float2bfloat16(r1 - __bfloat162float(h1)),
            __float2bfloat16(r2 - __bfloat162float(h2)));
    }
    {
        float x1 = qkv[qbase + D_MODEL], x2 = qkv[qbase + D_MODEL + 1];
        float r1 = x1 * c - x2 * s;
        float r2 = x2 * c + x1 * s;
        __nv_bfloat16 h1 = __float2bfloat16(r1), h2 = __float2bfloat16(r2);
        *(__nv_bfloat162*)&g_kh[obase] = __nv_bfloat162(h1, h2);
        *(__nv_bfloat162*)&g_kl[obase] = __nv_bfloat162(
            __float2bfloat16(r1 - __bfloat162float(h1)),
            __float2bfloat16(r2 - __bfloat162float(h2)));
    }
    {
        float x1 = qkv[qbase + 2 * D_MODEL], x2 = qkv[qbase + 2 * D_MODEL + 1];
        __nv_bfloat16 h1 = __float2bfloat16(x1), h2 = __float2bfloat16(x2);
        *(__nv_bfloat162*)&g_vh[obase] = __nv_bfloat162(h1, h2);
        *(__nv_bfloat162*)&g_vl[obase] = __nv_bfloat162(
            __float2bfloat16(x1 - __bfloat162float(h1)),
            __float2bfloat16(x2 - __bfloat162float(h2)));
    }
}

// ---------------------------------------------------------------------------
// Tensor-core flash attention, Br=128, Bc=64, 256 threads (8 warps).
// (a) tile loads use statically-selected source arrays with hoisted
// per-thread pointers; (b) batched ldmatrix (4 n-tiles) then term-major MMAs
// (same-acc distance 4) for both QK^T and PV.
// ---------------------------------------------------------------------------
#define ROWB 144                 // bytes per smem row (72 bf16)
#define ARRB (64 * ROWB)         // 9216 bytes per array
#define STAGEB (4 * ARRB)        // 36864 bytes per stage
#define ATTN_SMEM (2 * STAGEB)   // 73728

__global__ void __launch_bounds__(256, 2)
attn_mma_kernel(float* __restrict__ out) {
    extern __shared__ char smem[];

    int tid = threadIdx.x;
    int lane = tid & 31;
    int warp = tid >> 5;
    int g = lane >> 2;
    int tg = lane & 3;
    int li = lane & 15;
    int h = blockIdx.y;
    int t0 = (int)(gridDim.x - 1 - blockIdx.x) * 128;  // big workloads first
    int rg = t0 + warp * 16 + g;
    int rg8 = rg + 8;

    // --- Q fragments from precomputed hi/lo bf16 (scale pre-applied) ---
    uint32_t qh[4][4], ql[4][4];
#pragma unroll
    for (int ks = 0; ks < 4; ks++) {
        int c0 = h * C_HEAD + ks * 16 + 2 * tg;
#pragma unroll
        for (int ai = 0; ai < 4; ai++) {
            int r = (ai & 1) ? rg8 : rg;
            int c = c0 + ((ai & 2) ? 8 : 0);
            qh[ks][ai] = *(const uint32_t*)&g_qh[(size_t)r * D_MODEL + c];
            ql[ks][ai] = *(const uint32_t*)&g_ql[(size_t)r * D_MODEL + c];
        }
    }

    // --- hoisted cp.async source pointers / dest offsets (2 rows per array) ---
    int ld_row0 = tid >> 3;                 // 0..31
    int ld_c8 = tid & 7;
    size_t goff0 = (size_t)ld_row0 * D_MODEL + h * C_HEAD + ld_c8 * 8;
    size_t goff1 = goff0 + 32 * D_MODEL;    // row + 32
    const __nv_bfloat16* pKH0 = g_kh + goff0;  const __nv_bfloat16* pKH1 = g_kh + goff1;
    const __nv_bfloat16* pKL0 = g_kl + goff0;  const __nv_bfloat16* pKL1 = g_kl + goff1;
    const __nv_bfloat16* pVH0 = g_vh + goff0;  const __nv_bfloat16* pVH1 = g_vh + goff1;
    const __nv_bfloat16* pVL0 = g_vl + goff0;  const __nv_bfloat16* pVL1 = g_vl + goff1;
    uint32_t smem_base = smem_u32(smem);
    uint32_t d0 = smem_base + ld_row0 * ROWB + ld_c8 * 16;
    uint32_t d1 = d0 + 32 * ROWB;

    float O[8][4];
#pragma unroll
    for (int nt = 0; nt < 8; nt++)
#pragma unroll
        for (int j = 0; j < 4; j++) O[nt][j] = 0.f;
    float m0r = -1e30f, m1r = -1e30f, l0r = 0.f, l1r = 0.f;

    int smax = t0 + 64;     // last key-tile start (rows up to t0+127)

    // issue tile for s0, stage st (statically unrolled arrays)
#define ISSUE_TILE(st, s0)                                                  \
    do {                                                                    \
        size_t so = (size_t)(s0) * D_MODEL;                                 \
        uint32_t db = (st) * (uint32_t)STAGEB;                              \
        cpa16(d0 + db,            pKH0 + so);                               \
        cpa16(d1 + db,            pKH1 + so);                               \
        cpa16(d0 + db + ARRB,     pKL0 + so);                               \
        cpa16(d1 + db + ARRB,     pKL1 + so);                               \
        cpa16(d0 + db + 2 * ARRB, pVH0 + so);                               \
        cpa16(d1 + db + 2 * ARRB, pVH1 + so);                               \
        cpa16(d0 + db + 3 * ARRB, pVL0 + so);                               \
        cpa16(d1 + db + 3 * ARRB, pVL1 + so);                               \
    } while (0)

    ISSUE_TILE(0, 0);
    cpa_commit();

    // ldmatrix base addresses (stage 0); add STAGEB for stage 1
    uint32_t bKH = smem_base + (li & 7) * ROWB + ((li & 8) ? 16 : 0);
    uint32_t bVH = smem_base + 2 * ARRB + li * ROWB;

    int it = 0;
    for (int s0 = 0; s0 <= smax; s0 += 64, it++) {
        int cur = it & 1;
        if (s0 + 64 <= smax) {
            ISSUE_TILE(cur ^ 1, s0 + 64);
            cpa_commit();
            cpa_wait<1>();
        } else {
            cpa_wait<0>();
        }
        __syncthreads();

        uint32_t stb = cur * (uint32_t)STAGEB;
        uint32_t baseKH = bKH + stb;
        uint32_t baseKL = baseKH + ARRB;
        uint32_t baseVH = bVH + stb;
        uint32_t baseVL = baseVH + ARRB;

        // --- S = (Q/8) @ K^T : batched ldm (4 nt), term-major MMAs ---
        float sc[8][4];
#pragma unroll
        for (int nt = 0; nt < 8; nt++)
#pragma unroll
            for (int j = 0; j < 4; j++) sc[nt][j] = 0.f;

#pragma unroll
        for (int ks = 0; ks < 4; ks++) {
#pragma unroll
            for (int ntg = 0; ntg < 8; ntg += 4) {
                uint32_t kh2[4][2], kl2[4][2];
#pragma unroll
                for (int j = 0; j < 4; j++) {
                    uint32_t off = (uint32_t)((ntg + j) * 8 * ROWB + ks * 32);
                    ldm_x2(kh2[j][0], kh2[j][1], baseKH + off);
                    ldm_x2(kl2[j][0], kl2[j][1], baseKL + off);
                }
#pragma unroll
                for (int j = 0; j < 4; j++)
                    mma_bf16_16x8x16(sc[ntg + j], qh[ks], kh2[j][0], kh2[j][1]);
#pragma unroll
                for (int j = 0; j < 4; j++)
                    mma_bf16_16x8x16(sc[ntg + j], qh[ks], kl2[j][0], kl2[j][1]);
#pragma unroll
                for (int j = 0; j < 4; j++)
                    mma_bf16_16x8x16(sc[ntg + j], ql[ks], kh2[j][0], kh2[j][1]);
            }
        }

        // --- causal mask (tiles that can cross the diagonal for this warp) ---
        if (s0 + 63 > rg) {
#pragma unroll
            for (int nt = 0; nt < 8; nt++) {
                int col = s0 + nt * 8 + 2 * tg;
                if (col > rg)      sc[nt][0] = -1e30f;
                if (col + 1 > rg)  sc[nt][1] = -1e30f;
                if (col > rg8)     sc[nt][2] = -1e30f;
                if (col + 1 > rg8) sc[nt][3] = -1e30f;
            }
        }

        // --- online softmax (rows rg and rg8) ---
        float mx0 = m0r, mx1 = m1r;
#pragma unroll
        for (int nt = 0; nt < 8; nt++) {
            mx0 = fmaxf(mx0, fmaxf(sc[nt][0], sc[nt][1]));
            mx1 = fmaxf(mx1, fmaxf(sc[nt][2], sc[nt][3]));
        }
        mx0 = fmaxf(mx0, __shfl_xor_sync(0xffffffffu, mx0, 1));
        mx0 = fmaxf(mx0, __shfl_xor_sync(0xffffffffu, mx0, 2));
        mx1 = fmaxf(mx1, __shfl_xor_sync(0xffffffffu, mx1, 1));
        mx1 = fmaxf(mx1, __shfl_xor_sync(0xffffffffu, mx1, 2));

        float sum0 = 0.f, sum1 = 0.f;
#pragma unroll
        for (int nt = 0; nt < 8; nt++) {
            sc[nt][0] = __expf(sc[nt][0] - mx0);
            sc[nt][1] = __expf(sc[nt][1] - mx0);
            sc[nt][2] = __expf(sc[nt][2] - mx1);
            sc[nt][3] = __expf(sc[nt][3] - mx1);
            sum0 += sc[nt][0] + sc[nt][1];
            sum1 += sc[nt][2] + sc[nt][3];
        }
        sum0 += __shfl_xor_sync(0xffffffffu, sum0, 1);
        sum0 += __shfl_xor_sync(0xffffffffu, sum0, 2);
        sum1 += __shfl_xor_sync(0xffffffffu, sum1, 1);
        sum1 += __shfl_xor_sync(0xffffffffu, sum1, 2);

        float corr0 = __expf(m0r - mx0);
        float corr1 = __expf(m1r - mx1);
        l0r = l0r * corr0 + sum0;
        l1r = l1r * corr1 + sum1;
        m0r = mx0;
        m1r = mx1;
#pragma unroll
        for (int nt = 0; nt < 8; nt++) {
            O[nt][0] *= corr0;
            O[nt][1] *= corr0;
            O[nt][2] *= corr1;
            O[nt][3] *= corr1;
        }

        // --- O += P @ V : P hi/lo inline per ks; batched ldm; term-major ---
#pragma unroll
        for (int ks = 0; ks < 4; ks++) {
            uint32_t ph[4], pl[4];
#pragma unroll
            for (int half = 0; half < 2; half++) {
                int nt = 2 * ks + half;
                float p0 = sc[nt][0], p1 = sc[nt][1];
                float p2 = sc[nt][2], p3 = sc[nt][3];
                __nv_bfloat16 h0 = __float2bfloat16(p0), h1 = __float2bfloat16(p1);
                __nv_bfloat16 h2 = __float2bfloat16(p2), h3 = __float2bfloat16(p3);
                ph[0 + 2 * half] = pack_bf16(__bfloat162float(h0), __bfloat162float(h1));
                ph[1 + 2 * half] = pack_bf16(__bfloat162float(h2), __bfloat162float(h3));
                pl[0 + 2 * half] = pack_bf16(p0 - __bfloat162float(h0),
                                             p1 - __bfloat162float(h1));
                pl[1 + 2 * half] = pack_bf16(p2 - __bfloat162float(h2),
                                             p3 - __bfloat162float(h3));
            }
#pragma unroll
            for (int ntg = 0; ntg < 8; ntg += 4) {
                uint32_t vh2[4][2], vl2[4][2];
#pragma unroll
                for (int j = 0; j < 4; j++) {
                    uint32_t off = (uint32_t)(ks * 16 * ROWB + (ntg + j) * 16);
                    ldm_x2_trans(vh2[j][0], vh2[j][1], baseVH + off);
                    ldm_x2_trans(vl2[j][0], vl2[j][1], baseVL + off);
                }
#pragma unroll
                for (int j = 0; j < 4; j++)
                    mma_bf16_16x8x16(O[ntg + j], ph, vh2[j][0], vh2[j][1]);
#pragma unroll
                for (int j = 0; j < 4; j++)
                    mma_bf16_16x8x16(O[ntg + j], ph, vl2[j][0], vl2[j][1]);
#pragma unroll
                for (int j = 0; j < 4; j++)
                    mma_bf16_16x8x16(O[ntg + j], pl, vh2[j][0], vh2[j][1]);
            }
        }
        __syncthreads();
    }
#undef ISSUE_TILE

    // --- normalize + write ---
    float inv0 = 1.f / l0r;
    float inv1 = 1.f / l1r;
#pragma unroll
    for (int nt = 0; nt < 8; nt++) {
        int cb = h * C_HEAD + nt * 8 + 2 * tg;
        *(float2*)&out[(size_t)rg * D_MODEL + cb] =
            make_float2(O[nt][0] * inv0, O[nt][1] * inv0);
        *(float2*)&out[(size_t)rg8 * D_MODEL + cb] =
            make_float2(O[nt][2] * inv1, O[nt][3] * inv1);
    }
}

// ---------------------------------------------------------------------------
extern "C" void kernel_launch(void* const* d_in, const int* in_sizes, int n_in,
                              void* d_out, int out_size) {
    const float* x      = (const float*)d_in[0];   // [4096,1024]
    const float* W_qkv  = (const float*)d_in[1];   // [3072,1024]
    const float* W_proj = (const float*)d_in[2];   // [1024,1024]
    float* out = (float*)d_out;                    // [4096,1024]

    float* qkv_ptr;
    float* attn_ptr;
    cudaGetSymbolAddress((void**)&qkv_ptr, g_qkv);
    cudaGetSymbolAddress((void**)&attn_ptr, g_attn);

    cudaFuncSetAttribute(attn_mma_kernel, cudaFuncAttributeMaxDynamicSharedMemorySize,
                         ATTN_SMEM);

    // 1) qkv = x @ W_qkv^T   (tensor-core split-bf16)
    {
        dim3 grid(QKV_W / BNg, T_SEQ / BMg);
        gemm_nt_bf16x3_kernel<<<grid, 256>>>(x, W_qkv, qkv_ptr, T_SEQ, QKV_W, D_MODEL);
    }

    // 2) fused RoPE + hi/lo bf16 precompute
    {
        int total = T_SEQ * N_HEAD * (C_HEAD / 2);   // 2097152
        rope_convert_kernel<<<total / 256, 256>>>(qkv_ptr);
    }

    // 3) causal attention (tensor-core, cp.async pipelined)
    {
        dim3 grid(T_SEQ / 128, N_HEAD);
        attn_mma_kernel<<<grid, 256, ATTN_SMEM>>>(attn_ptr);
    }

    // 4) out = attn @ W_proj^T   (tensor-core split-bf16)
    {
        dim3 grid(D_MODEL / BNg, T_SEQ / BMg);
        gemm_nt_bf16x3_kernel<<<grid, 256>>>(attn_ptr, W_proj, out, T_SEQ, D_MODEL, D_MODEL);
    }
}